// round 11
// baseline (speedup 1.0000x reference)
#include <cuda_runtime.h>
#include <cuda_fp16.h>
#include <math.h>

#define NNODES 100000
#define NEDGES 1600000
#define FIN 128
#define FOUT 64
#define SCAN_NB ((NNODES + 1023) / 1024)   // 98
#define ASTR 72                             // smem row stride in halfs

typedef unsigned int u32;
typedef unsigned long long u64;

// ---------------- scratch (device globals; 16B-aligned) ----------------
__device__ __align__(16) int     g_ecnt[NNODES];
__device__ __align__(16) int     g_incl[NNODES];
__device__ __align__(16) int     g_bsum[SCAN_NB];
__device__ __align__(16) int     g_rowptr[NNODES + 1];
__device__ __align__(16) int     g_cursor[NNODES];
__device__ __align__(16) int     g_col[NEDGES];
__device__ __align__(16) float   g_dinv[NNODES];
__device__ __align__(16) __half2 g_h[NNODES * (FOUT / 2)];   // (x@W)*dinv, fp16 gather table
__device__ __align__(16) float   g_t1[NNODES * FOUT];        // x_temp (residual, fp32)
__device__ __align__(16) float   g_t2[NNODES * FOUT];        // layer-2 activation (fp32)
__device__ int g_is64;

__device__ __forceinline__ void acc_h2(float2& a, u32 h) {
    float2 f = __half22float2(*(const __half2*)&h);
    a.x += f.x; a.y += f.y;
}

// ---------------- dtype detector ----------------
__global__ void k_detect(const void* __restrict__ ei) {
    const unsigned long long* p = (const unsigned long long*)ei;
    __shared__ unsigned int s;
    if (threadIdx.x == 0) s = 0u;
    __syncthreads();
    unsigned int any = 0u;
    for (int i = threadIdx.x; i < 4096; i += 256)
        any |= (unsigned int)(p[i] >> 32);
    atomicOr(&s, any);
    __syncthreads();
    if (threadIdx.x == 0) g_is64 = (s == 0u) ? 1 : 0;
}

__device__ __forceinline__ int load_idx(const int* __restrict__ ei32, long long pos) {
    if (g_is64) return (int)((const long long*)ei32)[pos];
    return ei32[pos];
}

// ---------------- CSR build ----------------
__global__ void k_zero() {
    int i = blockIdx.x * blockDim.x + threadIdx.x;
    if (i < NNODES) g_ecnt[i] = 0;
}

__global__ void k_count(const int* __restrict__ ei32) {
    int e = blockIdx.x * blockDim.x + threadIdx.x;
    if (e < NEDGES) {
        int d = load_idx(ei32, (long long)NEDGES + e);
        if ((unsigned)d < (unsigned)NNODES) atomicAdd(&g_ecnt[d], 1);
    }
}

__global__ __launch_bounds__(1024) void k_scan1() {
    __shared__ int wsum[32];
    const int i    = blockIdx.x * 1024 + threadIdx.x;
    const int lane = threadIdx.x & 31;
    const int warp = threadIdx.x >> 5;
    int v = (i < NNODES) ? g_ecnt[i] : 0;
    int x = v;
#pragma unroll
    for (int o = 1; o < 32; o <<= 1) {
        int y = __shfl_up_sync(0xffffffffu, x, o);
        if (lane >= o) x += y;
    }
    if (lane == 31) wsum[warp] = x;
    __syncthreads();
    if (warp == 0) {
        int s = wsum[lane];
#pragma unroll
        for (int o = 1; o < 32; o <<= 1) {
            int y = __shfl_up_sync(0xffffffffu, s, o);
            if (lane >= o) s += y;
        }
        wsum[lane] = s;
    }
    __syncthreads();
    int incl = x + (warp > 0 ? wsum[warp - 1] : 0);
    if (i < NNODES) g_incl[i] = incl;
    if (threadIdx.x == 1023) g_bsum[blockIdx.x] = incl;
}

__global__ void k_scan2() {
    __shared__ int s[128];
    const int t = threadIdx.x;
    s[t] = (t < SCAN_NB) ? g_bsum[t] : 0;
    __syncthreads();
    for (int o = 1; o < 128; o <<= 1) {
        int x = s[t];
        int add = (t >= o) ? s[t - o] : 0;
        __syncthreads();
        s[t] = x + add;
        __syncthreads();
    }
    if (t < SCAN_NB) g_bsum[t] = (t == 0) ? 0 : s[t - 1];
    if (t == 0) g_rowptr[NNODES] = s[SCAN_NB - 1];
}

__global__ __launch_bounds__(1024) void k_scan3() {
    const int i = blockIdx.x * 1024 + threadIdx.x;
    if (i < NNODES) {
        int c = g_ecnt[i];
        int start = g_bsum[blockIdx.x] + g_incl[i] - c;
        g_rowptr[i] = start;
        g_cursor[i] = start;
        g_dinv[i]   = rsqrtf((float)(c + 1));
    }
}

__global__ void k_fill(const int* __restrict__ ei32) {
    int e = blockIdx.x * blockDim.x + threadIdx.x;
    if (e < NEDGES) {
        int d = load_idx(ei32, (long long)NEDGES + e);
        int s = load_idx(ei32, e);
        if ((unsigned)d < (unsigned)NNODES && (unsigned)s < (unsigned)NNODES) {
            int p = atomicAdd(&g_cursor[d], 1);
            g_col[p] = s;
        }
    }
}

// ---------------- HMMA GEMM: g_h[n,:] = half((X[n,:] @ W) * dinv[n]) ----------------
template <int K, int SEL>
__global__ __launch_bounds__(256) void k_gemm(const float* __restrict__ Xext,
                                              const float* __restrict__ W) {
    __shared__ __align__(16) __half Asm[128 * ASTR];
    __shared__ __align__(16) __half Bsm[64 * ASTR];

    const float* X;
    if constexpr (SEL == 0)      X = Xext;
    else if constexpr (SEL == 1) X = g_t1;
    else                         X = g_t2;

    const int tid  = threadIdx.x;
    const int warp = tid >> 5;
    const int lane = tid & 31;
    const int base = blockIdx.x * 128;
    const int wrow = warp * 16;
    const int qrow = lane >> 2;          // 0..7
    const int qk   = (lane & 3) * 2;     // 0,2,4,6

    float acc[8][4];
#pragma unroll
    for (int t = 0; t < 8; t++)
#pragma unroll
        for (int j = 0; j < 4; j++) acc[t][j] = 0.f;

    constexpr int NCH = K / 64;
#pragma unroll
    for (int ch = 0; ch < NCH; ch++) {
        const int kc = ch * 64;
        // stage A vectorized: 128 nodes x 16 float4 chunks
        for (int i = tid; i < 128 * 16; i += 256) {
            int r = i >> 4, c4 = (i & 15) * 4;
            int node = base + r;
            float4 v = make_float4(0.f, 0.f, 0.f, 0.f);
            if (node < NNODES)
                v = *(const float4*)&X[(size_t)node * K + kc + c4];
            __half2 h0 = __floats2half2_rn(v.x, v.y);
            __half2 h1 = __floats2half2_rn(v.z, v.w);
            u32 w0 = *(u32*)&h0, w1 = *(u32*)&h1;
            *(u64*)&Asm[r * ASTR + c4] = ((u64)w1 << 32) | (u64)w0;
        }
        // stage B transposed: Bsm[n][k] = W[kc+k][n]
        for (int i = tid; i < 64 * 64; i += 256) {
            int k = i >> 6, n = i & 63;
            Bsm[n * ASTR + k] = __float2half_rn(W[(size_t)(kc + k) * FOUT + n]);
        }
        __syncthreads();

#pragma unroll
        for (int s = 0; s < 4; s++) {
            const int k0 = s * 16;
            u32 a0 = *(const u32*)&Asm[(wrow + qrow)     * ASTR + k0 + qk];
            u32 a1 = *(const u32*)&Asm[(wrow + qrow + 8) * ASTR + k0 + qk];
            u32 a2 = *(const u32*)&Asm[(wrow + qrow)     * ASTR + k0 + qk + 8];
            u32 a3 = *(const u32*)&Asm[(wrow + qrow + 8) * ASTR + k0 + qk + 8];
#pragma unroll
            for (int t = 0; t < 8; t++) {
                u32 b0 = *(const u32*)&Bsm[(8 * t + qrow) * ASTR + k0 + qk];
                u32 b1 = *(const u32*)&Bsm[(8 * t + qrow) * ASTR + k0 + qk + 8];
                asm volatile(
                    "mma.sync.aligned.m16n8k16.row.col.f32.f16.f16.f32 "
                    "{%0,%1,%2,%3}, {%4,%5,%6,%7}, {%8,%9}, {%0,%1,%2,%3};"
                    : "+f"(acc[t][0]), "+f"(acc[t][1]), "+f"(acc[t][2]), "+f"(acc[t][3])
                    : "r"(a0), "r"(a1), "r"(a2), "r"(a3), "r"(b0), "r"(b1));
            }
        }
        if (ch + 1 < NCH) __syncthreads();
    }

    const int nlo = base + wrow + qrow;
    const int nhi = nlo + 8;
    const float dlo = (nlo < NNODES) ? g_dinv[nlo] : 0.f;
    const float dhi = (nhi < NNODES) ? g_dinv[nhi] : 0.f;
    const int cp = lane & 3;
#pragma unroll
    for (int t = 0; t < 8; t++) {
        int col = t * 4 + cp;
        if (nlo < NNODES)
            g_h[(size_t)nlo * 32 + col] = __floats2half2_rn(acc[t][0] * dlo, acc[t][1] * dlo);
        if (nhi < NNODES)
            g_h[(size_t)nhi * 32 + col] = __floats2half2_rn(acc[t][2] * dhi, acc[t][3] * dhi);
    }
}

// ---------------- aggregation: 4 edges per LDG.128 ----------------
// Warp layout: lane>>3 = edge slot (4 edges in parallel), lane&7 = 16B column slice.
// Each gather: uint4 = 8 cols fp16. Cross-slot combine via 2 shfl_xor rounds.
// MODE 0: identity -> g_t1 | MODE 1: relu -> g_t2 | MODE 2: relu + g_t1 -> ext out
template <int MODE>
__global__ __launch_bounds__(256) void k_agg(const float* __restrict__ bias,
                                             float* __restrict__ outext) {
    const int warp = threadIdx.x >> 5;
    const int lane = threadIdx.x & 31;
    const int node = blockIdx.x * 8 + warp;
    if (node >= NNODES) return;

    float* out;
    if constexpr (MODE == 0)      out = g_t1;
    else if constexpr (MODE == 1) out = g_t2;
    else                          out = outext;

    const int beg = g_rowptr[node];
    const int end = g_rowptr[node + 1];
    const int g   = lane >> 3;   // edge slot 0..3
    const int lg  = lane & 7;    // column slice: cols [lg*8, lg*8+8)

    float2 a0 = {0.f, 0.f}, a1 = {0.f, 0.f}, a2 = {0.f, 0.f}, a3 = {0.f, 0.f};

    for (int p = beg; p < end; p += 8) {
        const int i0 = p + g;
        const int i1 = p + 4 + g;
        int s0 = (i0 < end) ? g_col[i0] : -1;
        int s1 = (i1 < end) ? g_col[i1] : -1;
        if (s0 >= 0) {
            uint4 v = *(const uint4*)&g_h[(size_t)s0 * 32 + lg * 4];
            acc_h2(a0, v.x); acc_h2(a1, v.y); acc_h2(a2, v.z); acc_h2(a3, v.w);
        }
        if (s1 >= 0) {
            uint4 v = *(const uint4*)&g_h[(size_t)s1 * 32 + lg * 4];
            acc_h2(a0, v.x); acc_h2(a1, v.y); acc_h2(a2, v.z); acc_h2(a3, v.w);
        }
    }

    // combine the 4 edge slots (lanes L, L^8, L^16, L^24 hold same columns)
#pragma unroll
    for (int o = 8; o <= 16; o <<= 1) {
        a0.x += __shfl_xor_sync(0xffffffffu, a0.x, o);
        a0.y += __shfl_xor_sync(0xffffffffu, a0.y, o);
        a1.x += __shfl_xor_sync(0xffffffffu, a1.x, o);
        a1.y += __shfl_xor_sync(0xffffffffu, a1.y, o);
        a2.x += __shfl_xor_sync(0xffffffffu, a2.x, o);
        a2.y += __shfl_xor_sync(0xffffffffu, a2.y, o);
        a3.x += __shfl_xor_sync(0xffffffffu, a3.x, o);
        a3.y += __shfl_xor_sync(0xffffffffu, a3.y, o);
    }

    // self-loop (broadcast 16B load; identical in all 4 slot copies)
    {
        uint4 v = *(const uint4*)&g_h[(size_t)node * 32 + lg * 4];
        acc_h2(a0, v.x); acc_h2(a1, v.y); acc_h2(a2, v.z); acc_h2(a3, v.w);
    }

    if (lane < 8) {   // one copy stores
        const float di = g_dinv[node];
        const float4 bb0 = *(const float4*)&bias[lg * 8];
        const float4 bb1 = *(const float4*)&bias[lg * 8 + 4];
        float r0 = fmaf(di, a0.x, bb0.x), r1 = fmaf(di, a0.y, bb0.y);
        float r2 = fmaf(di, a1.x, bb0.z), r3 = fmaf(di, a1.y, bb0.w);
        float r4 = fmaf(di, a2.x, bb1.x), r5 = fmaf(di, a2.y, bb1.y);
        float r6 = fmaf(di, a3.x, bb1.z), r7 = fmaf(di, a3.y, bb1.w);
        if (MODE >= 1) {
            r0 = fmaxf(r0, 0.f); r1 = fmaxf(r1, 0.f); r2 = fmaxf(r2, 0.f); r3 = fmaxf(r3, 0.f);
            r4 = fmaxf(r4, 0.f); r5 = fmaxf(r5, 0.f); r6 = fmaxf(r6, 0.f); r7 = fmaxf(r7, 0.f);
        }
        if (MODE == 2) {
            const float4 t0 = *(const float4*)&g_t1[(size_t)node * FOUT + lg * 8];
            const float4 t1 = *(const float4*)&g_t1[(size_t)node * FOUT + lg * 8 + 4];
            r0 += t0.x; r1 += t0.y; r2 += t0.z; r3 += t0.w;
            r4 += t1.x; r5 += t1.y; r6 += t1.z; r7 += t1.w;
        }
        *(float4*)&out[(size_t)node * FOUT + lg * 8]     = make_float4(r0, r1, r2, r3);
        *(float4*)&out[(size_t)node * FOUT + lg * 8 + 4] = make_float4(r4, r5, r6, r7);
    }
}

// ---------------- launch ----------------
extern "C" void kernel_launch(void* const* d_in, const int* in_sizes, int n_in,
                              void* d_out, int out_size) {
    const float* x  = (const float*)d_in[0];
    const int*   ei = (const int*)d_in[1];     // int32 or int64; detected on device
    const float* W0 = (const float*)d_in[2];
    const float* b0 = (const float*)d_in[3];
    const float* Ws = (const float*)d_in[4];
    const float* bs = (const float*)d_in[5];
    float*       out = (float*)d_out;

    const int NB_N = (NNODES + 255) / 256;
    const int NB_E = (NEDGES + 255) / 256;
    const int NB_T = (NNODES + 127) / 128;   // 782 GEMM tiles
    const int NB_A = (NNODES + 7) / 8;       // 12500

    // CSR build (per call; deterministic)
    k_detect<<<1, 256>>>(ei);
    k_zero  <<<NB_N, 256>>>();
    k_count <<<NB_E, 256>>>(ei);
    k_scan1 <<<SCAN_NB, 1024>>>();
    k_scan2 <<<1, 128>>>();
    k_scan3 <<<SCAN_NB, 1024>>>();
    k_fill  <<<NB_E, 256>>>(ei);

    // layer 1: t1 = conv(x, W0, b0)
    k_gemm<FIN, 0> <<<NB_T, 256>>>(x, W0);
    k_agg<0>       <<<NB_A, 256>>>(b0, nullptr);

    // layer 2: t2 = relu(conv(t1, Ws[0], bs[0]))
    k_gemm<FOUT, 1><<<NB_T, 256>>>(nullptr, Ws);
    k_agg<1>       <<<NB_A, 256>>>(bs, nullptr);

    // layer 3: out = relu(conv(t2, Ws[1], bs[1])) + t1
    k_gemm<FOUT, 2><<<NB_T, 256>>>(nullptr, Ws + FOUT * FOUT);
    k_agg<2>       <<<NB_A, 256>>>(bs + FOUT, out);
}

// round 12
// speedup vs baseline: 1.3731x; 1.3731x over previous
#include <cuda_runtime.h>
#include <cuda_fp16.h>
#include <math.h>

#define NNODES 100000
#define NEDGES 1600000
#define FIN 128
#define FOUT 64
#define SCAN_NB ((NNODES + 1023) / 1024)   // 98
#define ASTR 72                             // smem row stride in halfs

typedef unsigned int u32;
typedef unsigned long long u64;

// ---------------- scratch (device globals; 16B-aligned) ----------------
__device__ __align__(16) int     g_ecnt[NNODES];
__device__ __align__(16) int     g_incl[NNODES];
__device__ __align__(16) int     g_bsum[SCAN_NB];
__device__ __align__(16) int     g_rowptr[NNODES + 1];
__device__ __align__(16) int     g_cursor[NNODES];
__device__ __align__(16) int     g_col[NEDGES];
__device__ __align__(16) float   g_dinv[NNODES];
__device__ __align__(16) __half2 g_h[NNODES * (FOUT / 2)];   // (x@W)*dinv, fp16 gather table
__device__ __align__(16) float   g_t1[NNODES * FOUT];        // x_temp (residual, fp32)
__device__ __align__(16) float   g_t2[NNODES * FOUT];        // layer-2 activation (fp32)
__device__ int g_is64;

// ---------------- zero + dtype detect (fused; block 0 detects) ----------------
__global__ void k_zero(const void* __restrict__ ei) {
    int i = blockIdx.x * blockDim.x + threadIdx.x;
    if (i < NNODES) g_ecnt[i] = 0;
    if (blockIdx.x == 0) {
        // int64 indices < 100000 have zero high words; int32 data reinterpreted
        // as int64 puts another (almost surely nonzero) index in the high word.
        const unsigned long long* p = (const unsigned long long*)ei;
        __shared__ unsigned int s;
        if (threadIdx.x == 0) s = 0u;
        __syncthreads();
        unsigned int any = 0u;
        for (int j = threadIdx.x; j < 4096; j += blockDim.x)
            any |= (unsigned int)(p[j] >> 32);
        atomicOr(&s, any);
        __syncthreads();
        if (threadIdx.x == 0) g_is64 = (s == 0u) ? 1 : 0;
    }
}

__device__ __forceinline__ int load_idx(const int* __restrict__ ei32, long long pos) {
    if (g_is64) return (int)((const long long*)ei32)[pos];
    return ei32[pos];
}

// ---------------- CSR build ----------------
__global__ void k_count(const int* __restrict__ ei32) {
    int e = blockIdx.x * blockDim.x + threadIdx.x;
    if (e < NEDGES) {
        int d = load_idx(ei32, (long long)NEDGES + e);
        if ((unsigned)d < (unsigned)NNODES) atomicAdd(&g_ecnt[d], 1);
    }
}

__global__ __launch_bounds__(1024) void k_scan1() {
    __shared__ int wsum[32];
    const int i    = blockIdx.x * 1024 + threadIdx.x;
    const int lane = threadIdx.x & 31;
    const int warp = threadIdx.x >> 5;
    int v = (i < NNODES) ? g_ecnt[i] : 0;
    int x = v;
#pragma unroll
    for (int o = 1; o < 32; o <<= 1) {
        int y = __shfl_up_sync(0xffffffffu, x, o);
        if (lane >= o) x += y;
    }
    if (lane == 31) wsum[warp] = x;
    __syncthreads();
    if (warp == 0) {
        int s = wsum[lane];
#pragma unroll
        for (int o = 1; o < 32; o <<= 1) {
            int y = __shfl_up_sync(0xffffffffu, s, o);
            if (lane >= o) s += y;
        }
        wsum[lane] = s;
    }
    __syncthreads();
    int incl = x + (warp > 0 ? wsum[warp - 1] : 0);
    if (i < NNODES) g_incl[i] = incl;
    if (threadIdx.x == 1023) g_bsum[blockIdx.x] = incl;
}

__global__ void k_scan2() {
    __shared__ int s[128];
    const int t = threadIdx.x;
    s[t] = (t < SCAN_NB) ? g_bsum[t] : 0;
    __syncthreads();
    for (int o = 1; o < 128; o <<= 1) {
        int x = s[t];
        int add = (t >= o) ? s[t - o] : 0;
        __syncthreads();
        s[t] = x + add;
        __syncthreads();
    }
    if (t < SCAN_NB) g_bsum[t] = (t == 0) ? 0 : s[t - 1];
    if (t == 0) g_rowptr[NNODES] = s[SCAN_NB - 1];
}

__global__ __launch_bounds__(1024) void k_scan3() {
    const int i = blockIdx.x * 1024 + threadIdx.x;
    if (i < NNODES) {
        int c = g_ecnt[i];
        int start = g_bsum[blockIdx.x] + g_incl[i] - c;
        g_rowptr[i] = start;
        g_cursor[i] = start;
        g_dinv[i]   = rsqrtf((float)(c + 1));
    }
}

__global__ void k_fill(const int* __restrict__ ei32) {
    int e = blockIdx.x * blockDim.x + threadIdx.x;
    if (e < NEDGES) {
        int d = load_idx(ei32, (long long)NEDGES + e);
        int s = load_idx(ei32, e);
        if ((unsigned)d < (unsigned)NNODES && (unsigned)s < (unsigned)NNODES) {
            int p = atomicAdd(&g_cursor[d], 1);
            g_col[p] = s;
        }
    }
}

// ---------------- HMMA GEMM: g_h[n,:] = half((X[n,:] @ W) * dinv[n]) ----------------
template <int K, int SEL>
__global__ __launch_bounds__(256) void k_gemm(const float* __restrict__ Xext,
                                              const float* __restrict__ W) {
    __shared__ __align__(16) __half Asm[128 * ASTR];
    __shared__ __align__(16) __half Bsm[64 * ASTR];

    const float* X;
    if constexpr (SEL == 0)      X = Xext;
    else if constexpr (SEL == 1) X = g_t1;
    else                         X = g_t2;

    const int tid  = threadIdx.x;
    const int warp = tid >> 5;
    const int lane = tid & 31;
    const int base = blockIdx.x * 128;
    const int wrow = warp * 16;
    const int qrow = lane >> 2;          // 0..7
    const int qk   = (lane & 3) * 2;     // 0,2,4,6

    float acc[8][4];
#pragma unroll
    for (int t = 0; t < 8; t++)
#pragma unroll
        for (int j = 0; j < 4; j++) acc[t][j] = 0.f;

    constexpr int NCH = K / 64;
#pragma unroll
    for (int ch = 0; ch < NCH; ch++) {
        const int kc = ch * 64;
        // stage A vectorized: 128 nodes x 16 float4 chunks
        for (int i = tid; i < 128 * 16; i += 256) {
            int r = i >> 4, c4 = (i & 15) * 4;
            int node = base + r;
            float4 v = make_float4(0.f, 0.f, 0.f, 0.f);
            if (node < NNODES)
                v = *(const float4*)&X[(size_t)node * K + kc + c4];
            __half2 h0 = __floats2half2_rn(v.x, v.y);
            __half2 h1 = __floats2half2_rn(v.z, v.w);
            u32 w0 = *(u32*)&h0, w1 = *(u32*)&h1;
            *(u64*)&Asm[r * ASTR + c4] = ((u64)w1 << 32) | (u64)w0;
        }
        // stage B transposed: Bsm[n][k] = W[kc+k][n]
        for (int i = tid; i < 64 * 64; i += 256) {
            int k = i >> 6, n = i & 63;
            Bsm[n * ASTR + k] = __float2half_rn(W[(size_t)(kc + k) * FOUT + n]);
        }
        __syncthreads();

#pragma unroll
        for (int s = 0; s < 4; s++) {
            const int k0 = s * 16;
            u32 a0 = *(const u32*)&Asm[(wrow + qrow)     * ASTR + k0 + qk];
            u32 a1 = *(const u32*)&Asm[(wrow + qrow + 8) * ASTR + k0 + qk];
            u32 a2 = *(const u32*)&Asm[(wrow + qrow)     * ASTR + k0 + qk + 8];
            u32 a3 = *(const u32*)&Asm[(wrow + qrow + 8) * ASTR + k0 + qk + 8];
#pragma unroll
            for (int t = 0; t < 8; t++) {
                u32 b0 = *(const u32*)&Bsm[(8 * t + qrow) * ASTR + k0 + qk];
                u32 b1 = *(const u32*)&Bsm[(8 * t + qrow) * ASTR + k0 + qk + 8];
                asm volatile(
                    "mma.sync.aligned.m16n8k16.row.col.f32.f16.f16.f32 "
                    "{%0,%1,%2,%3}, {%4,%5,%6,%7}, {%8,%9}, {%0,%1,%2,%3};"
                    : "+f"(acc[t][0]), "+f"(acc[t][1]), "+f"(acc[t][2]), "+f"(acc[t][3])
                    : "r"(a0), "r"(a1), "r"(a2), "r"(a3), "r"(b0), "r"(b1));
            }
        }
        if (ch + 1 < NCH) __syncthreads();
    }

    const int nlo = base + wrow + qrow;
    const int nhi = nlo + 8;
    const float dlo = (nlo < NNODES) ? g_dinv[nlo] : 0.f;
    const float dhi = (nhi < NNODES) ? g_dinv[nhi] : 0.f;
    const int cp = lane & 3;
#pragma unroll
    for (int t = 0; t < 8; t++) {
        int col = t * 4 + cp;
        if (nlo < NNODES)
            g_h[(size_t)nlo * 32 + col] = __floats2half2_rn(acc[t][0] * dlo, acc[t][1] * dlo);
        if (nhi < NNODES)
            g_h[(size_t)nhi * 32 + col] = __floats2half2_rn(acc[t][2] * dhi, acc[t][3] * dhi);
    }
}

// ---------------- aggregation (warp-per-node, MLP=8) ----------------
// out[i] = f(dinv[i]*(g_h[i] + sum_{src->i} g_h[src]) + bias); g_h is half2.
// 8 gathers issued back-to-back before any accumulation -> 8 outstanding loads.
// MODE 0: identity -> g_t1 | MODE 1: relu -> g_t2 | MODE 2: relu + g_t1 -> ext out
template <int MODE>
__global__ __launch_bounds__(256) void k_agg(const float* __restrict__ bias,
                                             float* __restrict__ outext) {
    const int warp = threadIdx.x >> 5;
    const int lane = threadIdx.x & 31;
    const int node = blockIdx.x * 8 + warp;
    if (node >= NNODES) return;

    float* out;
    if constexpr (MODE == 0)      out = g_t1;
    else if constexpr (MODE == 1) out = g_t2;
    else                          out = outext;

    const int beg = g_rowptr[node];
    const int end = g_rowptr[node + 1];

    float2 acc = __half22float2(g_h[(size_t)node * 32 + lane]);   // self-loop

    int p = beg;
    for (; p + 8 <= end; p += 8) {
        int s0 = g_col[p],     s1 = g_col[p + 1], s2 = g_col[p + 2], s3 = g_col[p + 3];
        int s4 = g_col[p + 4], s5 = g_col[p + 5], s6 = g_col[p + 6], s7 = g_col[p + 7];
        __half2 h0 = g_h[(size_t)s0 * 32 + lane];
        __half2 h1 = g_h[(size_t)s1 * 32 + lane];
        __half2 h2 = g_h[(size_t)s2 * 32 + lane];
        __half2 h3 = g_h[(size_t)s3 * 32 + lane];
        __half2 h4 = g_h[(size_t)s4 * 32 + lane];
        __half2 h5 = g_h[(size_t)s5 * 32 + lane];
        __half2 h6 = g_h[(size_t)s6 * 32 + lane];
        __half2 h7 = g_h[(size_t)s7 * 32 + lane];
        float2 b0 = __half22float2(h0), b1 = __half22float2(h1);
        float2 b2 = __half22float2(h2), b3 = __half22float2(h3);
        float2 b4 = __half22float2(h4), b5 = __half22float2(h5);
        float2 b6 = __half22float2(h6), b7 = __half22float2(h7);
        acc.x += ((b0.x + b1.x) + (b2.x + b3.x)) + ((b4.x + b5.x) + (b6.x + b7.x));
        acc.y += ((b0.y + b1.y) + (b2.y + b3.y)) + ((b4.y + b5.y) + (b6.y + b7.y));
    }
    for (; p + 4 <= end; p += 4) {
        int s0 = g_col[p], s1 = g_col[p + 1], s2 = g_col[p + 2], s3 = g_col[p + 3];
        float2 b0 = __half22float2(g_h[(size_t)s0 * 32 + lane]);
        float2 b1 = __half22float2(g_h[(size_t)s1 * 32 + lane]);
        float2 b2 = __half22float2(g_h[(size_t)s2 * 32 + lane]);
        float2 b3 = __half22float2(g_h[(size_t)s3 * 32 + lane]);
        acc.x += (b0.x + b1.x) + (b2.x + b3.x);
        acc.y += (b0.y + b1.y) + (b2.y + b3.y);
    }
    for (; p < end; p++) {
        int s = g_col[p];
        float2 b = __half22float2(g_h[(size_t)s * 32 + lane]);
        acc.x += b.x; acc.y += b.y;
    }

    const int off = 2 * lane;
    const float di = g_dinv[node];
    float2 bb = *(const float2*)&bias[off];
    float rx = fmaf(di, acc.x, bb.x);
    float ry = fmaf(di, acc.y, bb.y);
    if (MODE >= 1) { rx = fmaxf(rx, 0.f); ry = fmaxf(ry, 0.f); }
    if (MODE == 2) {
        float2 r = *(const float2*)&g_t1[(size_t)node * FOUT + off];
        rx += r.x; ry += r.y;
    }
    *(float2*)&out[(size_t)node * FOUT + off] = make_float2(rx, ry);
}

// ---------------- launch ----------------
extern "C" void kernel_launch(void* const* d_in, const int* in_sizes, int n_in,
                              void* d_out, int out_size) {
    const float* x  = (const float*)d_in[0];
    const int*   ei = (const int*)d_in[1];     // int32 or int64; detected on device
    const float* W0 = (const float*)d_in[2];
    const float* b0 = (const float*)d_in[3];
    const float* Ws = (const float*)d_in[4];
    const float* bs = (const float*)d_in[5];
    float*       out = (float*)d_out;

    const int NB_N = (NNODES + 255) / 256;
    const int NB_E = (NEDGES + 255) / 256;
    const int NB_T = (NNODES + 127) / 128;   // 782 GEMM tiles
    const int NB_A = (NNODES + 7) / 8;       // 12500

    // CSR build (per call; deterministic)
    k_zero  <<<NB_N, 256>>>(ei);             // fused dtype detect (block 0)
    k_count <<<NB_E, 256>>>(ei);
    k_scan1 <<<SCAN_NB, 1024>>>();
    k_scan2 <<<1, 128>>>();
    k_scan3 <<<SCAN_NB, 1024>>>();
    k_fill  <<<NB_E, 256>>>(ei);

    // layer 1: t1 = conv(x, W0, b0)
    k_gemm<FIN, 0> <<<NB_T, 256>>>(x, W0);
    k_agg<0>       <<<NB_A, 256>>>(b0, nullptr);

    // layer 2: t2 = relu(conv(t1, Ws[0], bs[0]))
    k_gemm<FOUT, 1><<<NB_T, 256>>>(nullptr, Ws);
    k_agg<1>       <<<NB_A, 256>>>(bs, nullptr);

    // layer 3: out = relu(conv(t2, Ws[1], bs[1])) + t1
    k_gemm<FOUT, 2><<<NB_T, 256>>>(nullptr, Ws + FOUT * FOUT);
    k_agg<2>       <<<NB_A, 256>>>(bs + FOUT, out);
}

// round 13
// speedup vs baseline: 1.4258x; 1.0384x over previous
#include <cuda_runtime.h>
#include <cuda_fp16.h>
#include <math.h>

#define NNODES 100000
#define NEDGES 1600000
#define FIN 128
#define FOUT 64
#define SCAN_NB ((NNODES + 1023) / 1024)   // 98
#define ASTR 72                             // smem row stride in halfs

typedef unsigned int u32;
typedef unsigned long long u64;

// ---------------- scratch (device globals; 16B-aligned) ----------------
__device__ __align__(16) int     g_ecnt[NNODES];
__device__ __align__(16) int     g_incl[NNODES];
__device__ __align__(16) int     g_bsum[SCAN_NB];
__device__ __align__(16) int     g_rowptr[NNODES + 1];
__device__ __align__(16) int     g_cursor[NNODES];
__device__ __align__(16) int     g_col[NEDGES];
__device__ __align__(16) float   g_dinv[NNODES];
__device__ __align__(16) __half2 g_h[NNODES * (FOUT / 2)];   // (x@W)*dinv, fp16 gather table
__device__ __align__(16) float   g_t1[NNODES * FOUT];        // x_temp (residual, fp32)
__device__ __align__(16) float   g_t2[NNODES * FOUT];        // layer-2 activation (fp32)
__device__ int g_is64;

// ---------------- zero + dtype detect (fused; block 0 detects) ----------------
__global__ void k_zero(const void* __restrict__ ei) {
    int i = blockIdx.x * blockDim.x + threadIdx.x;
    if (i < NNODES) g_ecnt[i] = 0;
    if (blockIdx.x == 0) {
        const unsigned long long* p = (const unsigned long long*)ei;
        __shared__ unsigned int s;
        if (threadIdx.x == 0) s = 0u;
        __syncthreads();
        unsigned int any = 0u;
        for (int j = threadIdx.x; j < 4096; j += blockDim.x)
            any |= (unsigned int)(p[j] >> 32);
        atomicOr(&s, any);
        __syncthreads();
        if (threadIdx.x == 0) g_is64 = (s == 0u) ? 1 : 0;
    }
}

__device__ __forceinline__ int load_idx(const int* __restrict__ ei32, long long pos) {
    if (g_is64) return (int)((const long long*)ei32)[pos];
    return ei32[pos];
}

// ---------------- CSR build ----------------
__global__ void k_count(const int* __restrict__ ei32) {
    int e = blockIdx.x * blockDim.x + threadIdx.x;
    if (e < NEDGES) {
        int d = load_idx(ei32, (long long)NEDGES + e);
        if ((unsigned)d < (unsigned)NNODES) atomicAdd(&g_ecnt[d], 1);
    }
}

__global__ __launch_bounds__(1024) void k_scan1() {
    __shared__ int wsum[32];
    const int i    = blockIdx.x * 1024 + threadIdx.x;
    const int lane = threadIdx.x & 31;
    const int warp = threadIdx.x >> 5;
    int v = (i < NNODES) ? g_ecnt[i] : 0;
    int x = v;
#pragma unroll
    for (int o = 1; o < 32; o <<= 1) {
        int y = __shfl_up_sync(0xffffffffu, x, o);
        if (lane >= o) x += y;
    }
    if (lane == 31) wsum[warp] = x;
    __syncthreads();
    if (warp == 0) {
        int s = wsum[lane];
#pragma unroll
        for (int o = 1; o < 32; o <<= 1) {
            int y = __shfl_up_sync(0xffffffffu, s, o);
            if (lane >= o) s += y;
        }
        wsum[lane] = s;
    }
    __syncthreads();
    int incl = x + (warp > 0 ? wsum[warp - 1] : 0);
    if (i < NNODES) g_incl[i] = incl;
    if (threadIdx.x == 1023) g_bsum[blockIdx.x] = incl;
}

__global__ void k_scan2() {
    __shared__ int s[128];
    const int t = threadIdx.x;
    s[t] = (t < SCAN_NB) ? g_bsum[t] : 0;
    __syncthreads();
    for (int o = 1; o < 128; o <<= 1) {
        int x = s[t];
        int add = (t >= o) ? s[t - o] : 0;
        __syncthreads();
        s[t] = x + add;
        __syncthreads();
    }
    if (t < SCAN_NB) g_bsum[t] = (t == 0) ? 0 : s[t - 1];
    if (t == 0) g_rowptr[NNODES] = s[SCAN_NB - 1];
}

__global__ __launch_bounds__(1024) void k_scan3() {
    const int i = blockIdx.x * 1024 + threadIdx.x;
    if (i < NNODES) {
        int c = g_ecnt[i];
        int start = g_bsum[blockIdx.x] + g_incl[i] - c;
        g_rowptr[i] = start;
        g_cursor[i] = start;
        g_dinv[i]   = rsqrtf((float)(c + 1));
    }
}

__global__ void k_fill(const int* __restrict__ ei32) {
    int e = blockIdx.x * blockDim.x + threadIdx.x;
    if (e < NEDGES) {
        int d = load_idx(ei32, (long long)NEDGES + e);
        int s = load_idx(ei32, e);
        if ((unsigned)d < (unsigned)NNODES && (unsigned)s < (unsigned)NNODES) {
            int p = atomicAdd(&g_cursor[d], 1);
            g_col[p] = s;
        }
    }
}

// ---------------- HMMA GEMM: g_h[n,:] = half((X[n,:] @ W) * dinv[n]) ----------------
template <int K, int SEL>
__global__ __launch_bounds__(256) void k_gemm(const float* __restrict__ Xext,
                                              const float* __restrict__ W) {
    __shared__ __align__(16) __half Asm[128 * ASTR];
    __shared__ __align__(16) __half Bsm[64 * ASTR];

    const float* X;
    if constexpr (SEL == 0)      X = Xext;
    else if constexpr (SEL == 1) X = g_t1;
    else                         X = g_t2;

    const int tid  = threadIdx.x;
    const int warp = tid >> 5;
    const int lane = tid & 31;
    const int base = blockIdx.x * 128;
    const int wrow = warp * 16;
    const int qrow = lane >> 2;          // 0..7
    const int qk   = (lane & 3) * 2;     // 0,2,4,6

    float acc[8][4];
#pragma unroll
    for (int t = 0; t < 8; t++)
#pragma unroll
        for (int j = 0; j < 4; j++) acc[t][j] = 0.f;

    constexpr int NCH = K / 64;
#pragma unroll
    for (int ch = 0; ch < NCH; ch++) {
        const int kc = ch * 64;
        for (int i = tid; i < 128 * 16; i += 256) {
            int r = i >> 4, c4 = (i & 15) * 4;
            int node = base + r;
            float4 v = make_float4(0.f, 0.f, 0.f, 0.f);
            if (node < NNODES)
                v = *(const float4*)&X[(size_t)node * K + kc + c4];
            __half2 h0 = __floats2half2_rn(v.x, v.y);
            __half2 h1 = __floats2half2_rn(v.z, v.w);
            u32 w0 = *(u32*)&h0, w1 = *(u32*)&h1;
            *(u64*)&Asm[r * ASTR + c4] = ((u64)w1 << 32) | (u64)w0;
        }
        for (int i = tid; i < 64 * 64; i += 256) {
            int k = i >> 6, n = i & 63;
            Bsm[n * ASTR + k] = __float2half_rn(W[(size_t)(kc + k) * FOUT + n]);
        }
        __syncthreads();

#pragma unroll
        for (int s = 0; s < 4; s++) {
            const int k0 = s * 16;
            u32 a0 = *(const u32*)&Asm[(wrow + qrow)     * ASTR + k0 + qk];
            u32 a1 = *(const u32*)&Asm[(wrow + qrow + 8) * ASTR + k0 + qk];
            u32 a2 = *(const u32*)&Asm[(wrow + qrow)     * ASTR + k0 + qk + 8];
            u32 a3 = *(const u32*)&Asm[(wrow + qrow + 8) * ASTR + k0 + qk + 8];
#pragma unroll
            for (int t = 0; t < 8; t++) {
                u32 b0 = *(const u32*)&Bsm[(8 * t + qrow) * ASTR + k0 + qk];
                u32 b1 = *(const u32*)&Bsm[(8 * t + qrow) * ASTR + k0 + qk + 8];
                asm volatile(
                    "mma.sync.aligned.m16n8k16.row.col.f32.f16.f16.f32 "
                    "{%0,%1,%2,%3}, {%4,%5,%6,%7}, {%8,%9}, {%0,%1,%2,%3};"
                    : "+f"(acc[t][0]), "+f"(acc[t][1]), "+f"(acc[t][2]), "+f"(acc[t][3])
                    : "r"(a0), "r"(a1), "r"(a2), "r"(a3), "r"(b0), "r"(b1));
            }
        }
        if (ch + 1 < NCH) __syncthreads();
    }

    const int nlo = base + wrow + qrow;
    const int nhi = nlo + 8;
    const float dlo = (nlo < NNODES) ? g_dinv[nlo] : 0.f;
    const float dhi = (nhi < NNODES) ? g_dinv[nhi] : 0.f;
    const int cp = lane & 3;
#pragma unroll
    for (int t = 0; t < 8; t++) {
        int col = t * 4 + cp;
        if (nlo < NNODES)
            g_h[(size_t)nlo * 32 + col] = __floats2half2_rn(acc[t][0] * dlo, acc[t][1] * dlo);
        if (nhi < NNODES)
            g_h[(size_t)nhi * 32 + col] = __floats2half2_rn(acc[t][2] * dhi, acc[t][3] * dhi);
    }
}

// ---------------- aggregation (warp-per-node, MLP=16) ----------------
// out[i] = f(dinv[i]*(g_h[i] + sum_{src->i} g_h[src]) + bias); g_h is half2.
// 16 gathers issued back-to-back before any accumulation -> 16 outstanding loads.
// MODE 0: identity -> g_t1 | MODE 1: relu -> g_t2 | MODE 2: relu + g_t1 -> ext out
template <int MODE>
__global__ __launch_bounds__(256) void k_agg(const float* __restrict__ bias,
                                             float* __restrict__ outext) {
    const int warp = threadIdx.x >> 5;
    const int lane = threadIdx.x & 31;
    const int node = blockIdx.x * 8 + warp;
    if (node >= NNODES) return;

    float* out;
    if constexpr (MODE == 0)      out = g_t1;
    else if constexpr (MODE == 1) out = g_t2;
    else                          out = outext;

    const int beg = g_rowptr[node];
    const int end = g_rowptr[node + 1];

    float2 acc = __half22float2(g_h[(size_t)node * 32 + lane]);   // self-loop

    int p = beg;
    for (; p + 16 <= end; p += 16) {
        int sx[16];
#pragma unroll
        for (int j = 0; j < 16; j++) sx[j] = g_col[p + j];
        __half2 h[16];
#pragma unroll
        for (int j = 0; j < 16; j++) h[j] = g_h[(size_t)sx[j] * 32 + lane];
        float sx0 = 0.f, sy0 = 0.f, sx1 = 0.f, sy1 = 0.f;
#pragma unroll
        for (int j = 0; j < 16; j += 2) {
            float2 f0 = __half22float2(h[j]);
            float2 f1 = __half22float2(h[j + 1]);
            sx0 += f0.x; sy0 += f0.y;
            sx1 += f1.x; sy1 += f1.y;
        }
        acc.x += sx0 + sx1;
        acc.y += sy0 + sy1;
    }
    for (; p + 8 <= end; p += 8) {
        int s0 = g_col[p],     s1 = g_col[p + 1], s2 = g_col[p + 2], s3 = g_col[p + 3];
        int s4 = g_col[p + 4], s5 = g_col[p + 5], s6 = g_col[p + 6], s7 = g_col[p + 7];
        __half2 h0 = g_h[(size_t)s0 * 32 + lane];
        __half2 h1 = g_h[(size_t)s1 * 32 + lane];
        __half2 h2 = g_h[(size_t)s2 * 32 + lane];
        __half2 h3 = g_h[(size_t)s3 * 32 + lane];
        __half2 h4 = g_h[(size_t)s4 * 32 + lane];
        __half2 h5 = g_h[(size_t)s5 * 32 + lane];
        __half2 h6 = g_h[(size_t)s6 * 32 + lane];
        __half2 h7 = g_h[(size_t)s7 * 32 + lane];
        float2 b0 = __half22float2(h0), b1 = __half22float2(h1);
        float2 b2 = __half22float2(h2), b3 = __half22float2(h3);
        float2 b4 = __half22float2(h4), b5 = __half22float2(h5);
        float2 b6 = __half22float2(h6), b7 = __half22float2(h7);
        acc.x += ((b0.x + b1.x) + (b2.x + b3.x)) + ((b4.x + b5.x) + (b6.x + b7.x));
        acc.y += ((b0.y + b1.y) + (b2.y + b3.y)) + ((b4.y + b5.y) + (b6.y + b7.y));
    }
    for (; p + 4 <= end; p += 4) {
        int s0 = g_col[p], s1 = g_col[p + 1], s2 = g_col[p + 2], s3 = g_col[p + 3];
        float2 b0 = __half22float2(g_h[(size_t)s0 * 32 + lane]);
        float2 b1 = __half22float2(g_h[(size_t)s1 * 32 + lane]);
        float2 b2 = __half22float2(g_h[(size_t)s2 * 32 + lane]);
        float2 b3 = __half22float2(g_h[(size_t)s3 * 32 + lane]);
        acc.x += (b0.x + b1.x) + (b2.x + b3.x);
        acc.y += (b0.y + b1.y) + (b2.y + b3.y);
    }
    for (; p < end; p++) {
        int s = g_col[p];
        float2 b = __half22float2(g_h[(size_t)s * 32 + lane]);
        acc.x += b.x; acc.y += b.y;
    }

    const int off = 2 * lane;
    const float di = g_dinv[node];
    float2 bb = *(const float2*)&bias[off];
    float rx = fmaf(di, acc.x, bb.x);
    float ry = fmaf(di, acc.y, bb.y);
    if (MODE >= 1) { rx = fmaxf(rx, 0.f); ry = fmaxf(ry, 0.f); }
    if (MODE == 2) {
        float2 r = *(const float2*)&g_t1[(size_t)node * FOUT + off];
        rx += r.x; ry += r.y;
    }
    *(float2*)&out[(size_t)node * FOUT + off] = make_float2(rx, ry);
}

// ---------------- launch ----------------
extern "C" void kernel_launch(void* const* d_in, const int* in_sizes, int n_in,
                              void* d_out, int out_size) {
    const float* x  = (const float*)d_in[0];
    const int*   ei = (const int*)d_in[1];     // int32 or int64; detected on device
    const float* W0 = (const float*)d_in[2];
    const float* b0 = (const float*)d_in[3];
    const float* Ws = (const float*)d_in[4];
    const float* bs = (const float*)d_in[5];
    float*       out = (float*)d_out;

    const int NB_N = (NNODES + 255) / 256;
    const int NB_E = (NEDGES + 255) / 256;
    const int NB_T = (NNODES + 127) / 128;   // 782 GEMM tiles
    const int NB_A = (NNODES + 7) / 8;       // 12500

    // CSR build (per call; deterministic)
    k_zero  <<<NB_N, 256>>>(ei);             // fused dtype detect (block 0)
    k_count <<<NB_E, 256>>>(ei);
    k_scan1 <<<SCAN_NB, 1024>>>();
    k_scan2 <<<1, 128>>>();
    k_scan3 <<<SCAN_NB, 1024>>>();
    k_fill  <<<NB_E, 256>>>(ei);

    // layer 1: t1 = conv(x, W0, b0)
    k_gemm<FIN, 0> <<<NB_T, 256>>>(x, W0);
    k_agg<0>       <<<NB_A, 256>>>(b0, nullptr);

    // layer 2: t2 = relu(conv(t1, Ws[0], bs[0]))
    k_gemm<FOUT, 1><<<NB_T, 256>>>(nullptr, Ws);
    k_agg<1>       <<<NB_A, 256>>>(bs, nullptr);

    // layer 3: out = relu(conv(t2, Ws[1], bs[1])) + t1
    k_gemm<FOUT, 2><<<NB_T, 256>>>(nullptr, Ws + FOUT * FOUT);
    k_agg<2>       <<<NB_A, 256>>>(bs + FOUT, out);
}